// round 6
// baseline (speedup 1.0000x reference)
#include <cuda_runtime.h>
#include <math.h>

#define N_NODES 100000
#define F_OUT 64   // both layers output 64 features

// ---------------- scratch (static __device__, no allocation) ----------------
__device__ int    g_deg_out[N_NODES];
__device__ int    g_deg_in[N_NODES];
__device__ float  g_rs_out[N_NODES];
__device__ float  g_rs_in[N_NODES];
__device__ float4 g_y[N_NODES * 16];    // GEMM output buffer (reused by both layers)
__device__ float4 g_agg[N_NODES * 16];  // layer-1 scatter accumulator

// ---------------- zero kernels ----------------
__global__ void zero_deg_kernel() {
    int i = blockIdx.x * blockDim.x + threadIdx.x;
    if (i < N_NODES) { g_deg_out[i] = 0; g_deg_in[i] = 0; }
}

__global__ void zero_agg_kernel() {
    int i = blockIdx.x * blockDim.x + threadIdx.x;
    if (i < N_NODES * 16) g_agg[i] = make_float4(0.f, 0.f, 0.f, 0.f);
}

__global__ void zero_ptr_kernel(float4* __restrict__ p, int n4) {
    int i = blockIdx.x * blockDim.x + threadIdx.x;
    if (i < n4) p[i] = make_float4(0.f, 0.f, 0.f, 0.f);
}

// ---------------- degrees ----------------
__global__ void degree_kernel(const int* __restrict__ src, const int* __restrict__ dst, int E) {
    int e = blockIdx.x * blockDim.x + threadIdx.x;
    if (e < E) {
        atomicAdd(&g_deg_out[src[e]], 1);
        atomicAdd(&g_deg_in[dst[e]], 1);
    }
}

__global__ void rsqrt_kernel() {
    int i = blockIdx.x * blockDim.x + threadIdx.x;
    if (i < N_NODES) {
        g_rs_out[i] = rsqrtf((float)max(g_deg_out[i], 1));
        g_rs_in[i]  = rsqrtf((float)max(g_deg_in[i], 1));
    }
}

// ---------------- GEMM: Y[n,64] = transform(X[n,:]) @ W ----------------
// LAYER2=false: X = Xext (input features), transform = x * rs_out[n]     (K = 128)
// LAYER2=true : X = g_agg (DEVICE symbol, resolved on-device!),
//               transform = relu(x * rs_in[n] + b_prev) * rs_out[n]      (K = 64)
// One thread per node, 128 nodes per block, W + padded x-tile in dynamic smem.
template <int K, bool LAYER2>
__global__ __launch_bounds__(128) void gemm_kernel(
    const float* __restrict__ Xext, const float* __restrict__ W,
    const float* __restrict__ bias_prev)
{
    extern __shared__ float smem[];
    float* Ws = smem;                    // K*64 floats
    float* xs = smem + K * 64;           // 128*(K+1) floats (padded rows)
    const int tid = threadIdx.x;
    const int node0 = blockIdx.x * 128;

    // CRITICAL: g_agg referenced in DEVICE code (host-side &g_agg is the host
    // shadow symbol, which GB300's ATS happily reads as zeros — the round-5 bug)
    const float* X = LAYER2 ? (const float*)g_agg : Xext;

    // load W (coalesced float4)
    for (int i = tid; i < K * 16; i += 128)
        ((float4*)Ws)[i] = ((const float4*)W)[i];

    // load + transform x tile into padded smem
    constexpr int K4 = K / 4;
    for (int i = tid; i < 128 * K4; i += 128) {
        int r = i / K4;
        int c4 = i % K4;
        int node = node0 + r;
        float4 v = make_float4(0.f, 0.f, 0.f, 0.f);
        if (node < N_NODES) {
            v = ((const float4*)X)[(size_t)node * K4 + c4];
            if (LAYER2) {
                float ri = g_rs_in[node];
                float ro = g_rs_out[node];
                float4 bb = ((const float4*)bias_prev)[c4];
                v.x = fmaxf(fmaf(v.x, ri, bb.x), 0.f) * ro;
                v.y = fmaxf(fmaf(v.y, ri, bb.y), 0.f) * ro;
                v.z = fmaxf(fmaf(v.z, ri, bb.z), 0.f) * ro;
                v.w = fmaxf(fmaf(v.w, ri, bb.w), 0.f) * ro;
            } else {
                float ro = g_rs_out[node];
                v.x *= ro; v.y *= ro; v.z *= ro; v.w *= ro;
            }
        }
        float* xr = xs + r * (K + 1) + c4 * 4;
        xr[0] = v.x; xr[1] = v.y; xr[2] = v.z; xr[3] = v.w;
    }
    __syncthreads();

    float acc[64];
#pragma unroll
    for (int j = 0; j < 64; j++) acc[j] = 0.f;

    const float4* Ws4 = (const float4*)Ws;
    const float* xrow = xs + tid * (K + 1);
#pragma unroll 4
    for (int k = 0; k < K; k++) {
        float xv = xrow[k];
#pragma unroll
        for (int j4 = 0; j4 < 16; j4++) {
            float4 w = Ws4[k * 16 + j4];
            acc[j4 * 4 + 0] = fmaf(xv, w.x, acc[j4 * 4 + 0]);
            acc[j4 * 4 + 1] = fmaf(xv, w.y, acc[j4 * 4 + 1]);
            acc[j4 * 4 + 2] = fmaf(xv, w.z, acc[j4 * 4 + 2]);
            acc[j4 * 4 + 3] = fmaf(xv, w.w, acc[j4 * 4 + 3]);
        }
    }

    int node = node0 + tid;
    if (node < N_NODES) {
        float4* out4 = &g_y[(size_t)node * 16];
#pragma unroll
        for (int j4 = 0; j4 < 16; j4++)
            out4[j4] = make_float4(acc[j4 * 4 + 0], acc[j4 * 4 + 1],
                                   acc[j4 * 4 + 2], acc[j4 * 4 + 3]);
    }
}

// ---------------- edge scatter: dest[dst] += g_y[src] ----------------
// 16 threads per edge, one float4 vector reduction each (red.global.add.v4.f32)
template <bool TO_AGG>
__global__ void scatter_kernel(const int* __restrict__ src, const int* __restrict__ dst,
                               float* __restrict__ out, int E)
{
    int g = blockIdx.x * blockDim.x + threadIdx.x;
    int e = g >> 4;
    int part = g & 15;
    if (e >= E) return;
    int s = __ldg(&src[e]);
    int d = __ldg(&dst[e]);
    float4 v = g_y[(size_t)s * 16 + part];
    float* p;
    if (TO_AGG) p = (float*)&g_agg[(size_t)d * 16 + part];   // device-side symbol ref: OK
    else        p = out + ((size_t)d * 64 + part * 4);
    asm volatile("red.global.add.v4.f32 [%0], {%1,%2,%3,%4};"
                 :: "l"(p), "f"(v.x), "f"(v.y), "f"(v.z), "f"(v.w)
                 : "memory");
}

// ---------------- finalize: out = out * rs_in[row] + b2 ----------------
__global__ void finalize_kernel(float4* __restrict__ out, const float* __restrict__ b2) {
    int i = blockIdx.x * blockDim.x + threadIdx.x;
    if (i < N_NODES * 16) {
        int row = i >> 4;
        int c4 = i & 15;
        float ri = g_rs_in[row];
        float4 bb = ((const float4*)b2)[c4];
        float4 v = out[i];
        v.x = fmaf(v.x, ri, bb.x);
        v.y = fmaf(v.y, ri, bb.y);
        v.z = fmaf(v.z, ri, bb.z);
        v.w = fmaf(v.w, ri, bb.w);
        out[i] = v;
    }
}

// ---------------- launch ----------------
extern "C" void kernel_launch(void* const* d_in, const int* in_sizes, int n_in,
                              void* d_out, int out_size)
{
    // Positional defaults (setup_inputs dict order)
    const float* x   = (const float*)d_in[0];
    const int*   src = (const int*)d_in[1];
    const int*   dst = (const int*)d_in[2];
    const float* W1  = (const float*)d_in[3];
    const float* b1  = (const float*)d_in[4];
    const float* W2  = (const float*)d_in[5];
    const float* b2  = (const float*)d_in[6];
    int E = in_sizes[1];

    // Size-based identification (robust to metadata reordering; src/dst and
    // b1/b2 keep their relative order among equal-sized entries)
    {
        int e_seen = 0, b_seen = 0;
        for (int i = 0; i < n_in; i++) {
            int s = in_sizes[i];
            if      (s == N_NODES * 128) x  = (const float*)d_in[i];
            else if (s == 128 * 64)      W1 = (const float*)d_in[i];
            else if (s == 64 * 64)       W2 = (const float*)d_in[i];
            else if (s == 64) { if (b_seen++ == 0) b1 = (const float*)d_in[i];
                                else               b2 = (const float*)d_in[i]; }
            else if (s > 64 * 64 && s != N_NODES * 128) {
                if (e_seen++ == 0) { src = (const int*)d_in[i]; E = s; }
                else                 dst = (const int*)d_in[i];
            }
        }
    }
    float* out = (float*)d_out;

    const int smem1 = (128 * 64 + 128 * 129) * (int)sizeof(float);  // 98816 B
    const int smem2 = (64 * 64 + 128 * 65) * (int)sizeof(float);    // 49664 B
    cudaFuncSetAttribute(gemm_kernel<128, false>,
                         cudaFuncAttributeMaxDynamicSharedMemorySize, smem1);
    cudaFuncSetAttribute(gemm_kernel<64, true>,
                         cudaFuncAttributeMaxDynamicSharedMemorySize, smem2);

    const int NB_N    = (N_NODES + 255) / 256;
    const int NB_N16  = (N_NODES * 16 + 255) / 256;
    const int NB_E    = (E + 255) / 256;
    const int NB_E16  = (E * 16 + 255) / 256;
    const int NB_GEMM = (N_NODES + 127) / 128;

    // degrees + norms
    zero_deg_kernel<<<NB_N, 256>>>();
    degree_kernel<<<NB_E, 256>>>(src, dst, E);
    rsqrt_kernel<<<NB_N, 256>>>();

    // layer 1: y = (x * rs_out) @ W1 ; agg[dst] += y[src]
    zero_agg_kernel<<<NB_N16, 256>>>();
    gemm_kernel<128, false><<<NB_GEMM, 128, smem1>>>(x, W1, nullptr);
    scatter_kernel<true><<<NB_E16, 256>>>(src, dst, nullptr, E);

    // layer 2: h = relu(agg * rs_in + b1); y = (h * rs_out) @ W2 ; out[dst] += y[src]
    zero_ptr_kernel<<<NB_N16, 256>>>((float4*)out, N_NODES * 16);
    gemm_kernel<64, true><<<NB_GEMM, 128, smem2>>>(nullptr, W2, b1);
    scatter_kernel<false><<<NB_E16, 256>>>(src, dst, out, E);

    // out = out * rs_in + b2
    finalize_kernel<<<NB_N16, 256>>>((float4*)out, b2);
}

// round 9
// speedup vs baseline: 1.3600x; 1.3600x over previous
#include <cuda_runtime.h>
#include <math.h>

#define N_NODES 100000
#define E_MAX   1600000
#define SCAN_BLOCKS ((N_NODES + 255) / 256)   // 391

// ---------------- scratch (static __device__, no allocation) ----------------
__device__ int    g_deg_out[N_NODES];
__device__ int    g_deg_in[N_NODES];
__device__ float  g_rs_out[N_NODES];
__device__ float  g_rs_in[N_NODES];
__device__ float4 g_y[N_NODES * 16];    // GEMM output buffer (reused by both layers)
__device__ float4 g_agg[N_NODES * 16];  // layer-1 gather result
__device__ int    g_row_ptr[N_NODES];   // CSR row starts (by dst)
__device__ int    g_cursor[N_NODES];    // fill cursors
__device__ int    g_col[E_MAX];         // CSR column indices (= src node)
__device__ int    g_partials[SCAN_BLOCKS];

// ---------------- degrees ----------------
__global__ void zero_deg_kernel() {
    int i = blockIdx.x * blockDim.x + threadIdx.x;
    if (i < N_NODES) { g_deg_out[i] = 0; g_deg_in[i] = 0; }
}

__global__ void degree_kernel(const int* __restrict__ src, const int* __restrict__ dst, int E) {
    int e = blockIdx.x * blockDim.x + threadIdx.x;
    if (e < E) {
        atomicAdd(&g_deg_out[src[e]], 1);
        atomicAdd(&g_deg_in[dst[e]], 1);
    }
}

__global__ void rsqrt_kernel() {
    int i = blockIdx.x * blockDim.x + threadIdx.x;
    if (i < N_NODES) {
        g_rs_out[i] = rsqrtf((float)max(g_deg_out[i], 1));
        g_rs_in[i]  = rsqrtf((float)max(g_deg_in[i], 1));
    }
}

// ---------------- CSR build: 2-level exclusive scan of deg_in + fill ----------------
__global__ void scan_blocks_kernel() {
    __shared__ int sh[256];
    int t = threadIdx.x;
    int i = blockIdx.x * 256 + t;
    int v = (i < N_NODES) ? g_deg_in[i] : 0;
    sh[t] = v;
    __syncthreads();
#pragma unroll
    for (int off = 1; off < 256; off <<= 1) {
        int cur = sh[t];
        int add = (t >= off) ? sh[t - off] : 0;
        __syncthreads();
        sh[t] = cur + add;
        __syncthreads();
    }
    if (i < N_NODES) g_row_ptr[i] = sh[t] - v;      // block-local exclusive
    if (t == 255) g_partials[blockIdx.x] = sh[255]; // block total
}

__global__ void scan_partials_kernel() {
    __shared__ int sh[512];
    int t = threadIdx.x;
    int v = (t < SCAN_BLOCKS) ? g_partials[t] : 0;
    sh[t] = v;
    __syncthreads();
#pragma unroll
    for (int off = 1; off < 512; off <<= 1) {
        int cur = sh[t];
        int add = (t >= off) ? sh[t - off] : 0;
        __syncthreads();
        sh[t] = cur + add;
        __syncthreads();
    }
    if (t < SCAN_BLOCKS) g_partials[t] = sh[t] - v; // exclusive block offsets
}

__global__ void scan_add_kernel() {
    int i = blockIdx.x * blockDim.x + threadIdx.x;
    if (i < N_NODES) {
        int r = g_row_ptr[i] + g_partials[i >> 8];
        g_row_ptr[i] = r;
        g_cursor[i]  = r;
    }
}

__global__ void csr_fill_kernel(const int* __restrict__ src, const int* __restrict__ dst, int E) {
    int e = blockIdx.x * blockDim.x + threadIdx.x;
    if (e < E) {
        int d = dst[e];
        int pos = atomicAdd(&g_cursor[d], 1);
        g_col[pos] = src[e];
    }
}

// ---------------- GEMM: Y[n,64] = transform(X[n,:]) @ W ----------------
// LAYER2=false: X = Xext, transform = x * rs_out[n]                     (K = 128)
// LAYER2=true : X = g_agg (device-side symbol ref — NOT from host!),
//               transform = relu(x * rs_in[n] + b_prev) * rs_out[n]     (K = 64)
template <int K, bool LAYER2>
__global__ __launch_bounds__(128) void gemm_kernel(
    const float* __restrict__ Xext, const float* __restrict__ W,
    const float* __restrict__ bias_prev)
{
    extern __shared__ float smem[];
    float* Ws = smem;                    // K*64 floats
    float* xs = smem + K * 64;           // 128*(K+1) floats (padded rows)
    const int tid = threadIdx.x;
    const int node0 = blockIdx.x * 128;

    const float* X = LAYER2 ? (const float*)g_agg : Xext;

    for (int i = tid; i < K * 16; i += 128)
        ((float4*)Ws)[i] = ((const float4*)W)[i];

    constexpr int K4 = K / 4;
    for (int i = tid; i < 128 * K4; i += 128) {
        int r = i / K4;
        int c4 = i % K4;
        int node = node0 + r;
        float4 v = make_float4(0.f, 0.f, 0.f, 0.f);
        if (node < N_NODES) {
            v = ((const float4*)X)[(size_t)node * K4 + c4];
            if (LAYER2) {
                float ri = g_rs_in[node];
                float ro = g_rs_out[node];
                float4 bb = ((const float4*)bias_prev)[c4];
                v.x = fmaxf(fmaf(v.x, ri, bb.x), 0.f) * ro;
                v.y = fmaxf(fmaf(v.y, ri, bb.y), 0.f) * ro;
                v.z = fmaxf(fmaf(v.z, ri, bb.z), 0.f) * ro;
                v.w = fmaxf(fmaf(v.w, ri, bb.w), 0.f) * ro;
            } else {
                float ro = g_rs_out[node];
                v.x *= ro; v.y *= ro; v.z *= ro; v.w *= ro;
            }
        }
        float* xr = xs + r * (K + 1) + c4 * 4;
        xr[0] = v.x; xr[1] = v.y; xr[2] = v.z; xr[3] = v.w;
    }
    __syncthreads();

    float acc[64];
#pragma unroll
    for (int j = 0; j < 64; j++) acc[j] = 0.f;

    const float4* Ws4 = (const float4*)Ws;
    const float* xrow = xs + tid * (K + 1);
#pragma unroll 4
    for (int k = 0; k < K; k++) {
        float xv = xrow[k];
#pragma unroll
        for (int j4 = 0; j4 < 16; j4++) {
            float4 w = Ws4[k * 16 + j4];
            acc[j4 * 4 + 0] = fmaf(xv, w.x, acc[j4 * 4 + 0]);
            acc[j4 * 4 + 1] = fmaf(xv, w.y, acc[j4 * 4 + 1]);
            acc[j4 * 4 + 2] = fmaf(xv, w.z, acc[j4 * 4 + 2]);
            acc[j4 * 4 + 3] = fmaf(xv, w.w, acc[j4 * 4 + 3]);
        }
    }

    int node = node0 + tid;
    if (node < N_NODES) {
        float4* out4 = &g_y[(size_t)node * 16];
#pragma unroll
        for (int j4 = 0; j4 < 16; j4++)
            out4[j4] = make_float4(acc[j4 * 4 + 0], acc[j4 * 4 + 1],
                                   acc[j4 * 4 + 2], acc[j4 * 4 + 3]);
    }
}

// ---------------- CSR gather: dest[n] = sum over in-edges of g_y[src] ----------------
// 16 threads per node (one float4 part each); 8 nodes per 128-thread block.
// FINAL=false: write raw sum to g_agg.
// FINAL=true : write sum * rs_in[n] + b2 to out.
template <bool FINAL>
__global__ __launch_bounds__(128) void gather_kernel(float4* __restrict__ outp,
                                                     const float* __restrict__ b2)
{
    const int tid  = threadIdx.x;
    const int node = blockIdx.x * 8 + (tid >> 4);
    const int part = tid & 15;
    if (node >= N_NODES) return;

    const int start = g_row_ptr[node];
    const int deg   = g_deg_in[node];

    float4 acc = make_float4(0.f, 0.f, 0.f, 0.f);
    float4 acc2 = make_float4(0.f, 0.f, 0.f, 0.f);
    int e = start;
    // 2-way unroll with independent accumulators for MLP
    for (; e + 1 < start + deg; e += 2) {
        int s0 = __ldg(&g_col[e]);
        int s1 = __ldg(&g_col[e + 1]);
        float4 v0 = g_y[(size_t)s0 * 16 + part];
        float4 v1 = g_y[(size_t)s1 * 16 + part];
        acc.x += v0.x;  acc.y += v0.y;  acc.z += v0.z;  acc.w += v0.w;
        acc2.x += v1.x; acc2.y += v1.y; acc2.z += v1.z; acc2.w += v1.w;
    }
    if (e < start + deg) {
        int s0 = __ldg(&g_col[e]);
        float4 v0 = g_y[(size_t)s0 * 16 + part];
        acc.x += v0.x; acc.y += v0.y; acc.z += v0.z; acc.w += v0.w;
    }
    acc.x += acc2.x; acc.y += acc2.y; acc.z += acc2.z; acc.w += acc2.w;

    if (FINAL) {
        float ri = g_rs_in[node];
        float4 bb = ((const float4*)b2)[part];
        acc.x = fmaf(acc.x, ri, bb.x);
        acc.y = fmaf(acc.y, ri, bb.y);
        acc.z = fmaf(acc.z, ri, bb.z);
        acc.w = fmaf(acc.w, ri, bb.w);
        outp[(size_t)node * 16 + part] = acc;
    } else {
        g_agg[(size_t)node * 16 + part] = acc;
    }
}

// ---------------- launch ----------------
extern "C" void kernel_launch(void* const* d_in, const int* in_sizes, int n_in,
                              void* d_out, int out_size)
{
    // Positional defaults (setup_inputs dict order)
    const float* x   = (const float*)d_in[0];
    const int*   src = (const int*)d_in[1];
    const int*   dst = (const int*)d_in[2];
    const float* W1  = (const float*)d_in[3];
    const float* b1  = (const float*)d_in[4];
    const float* W2  = (const float*)d_in[5];
    const float* b2  = (const float*)d_in[6];
    int E = in_sizes[1];

    // Size-based identification (robust to metadata reordering)
    {
        int e_seen = 0, b_seen = 0;
        for (int i = 0; i < n_in; i++) {
            int s = in_sizes[i];
            if      (s == N_NODES * 128) x  = (const float*)d_in[i];
            else if (s == 128 * 64)      W1 = (const float*)d_in[i];
            else if (s == 64 * 64)       W2 = (const float*)d_in[i];
            else if (s == 64) { if (b_seen++ == 0) b1 = (const float*)d_in[i];
                                else               b2 = (const float*)d_in[i]; }
            else if (s > 64 * 64 && s != N_NODES * 128) {
                if (e_seen++ == 0) { src = (const int*)d_in[i]; E = s; }
                else                 dst = (const int*)d_in[i];
            }
        }
    }
    float* out = (float*)d_out;

    const int smem1 = (128 * 64 + 128 * 129) * (int)sizeof(float);  // 98816 B
    const int smem2 = (64 * 64 + 128 * 65) * (int)sizeof(float);    // 49664 B
    cudaFuncSetAttribute(gemm_kernel<128, false>,
                         cudaFuncAttributeMaxDynamicSharedMemorySize, smem1);
    cudaFuncSetAttribute(gemm_kernel<64, true>,
                         cudaFuncAttributeMaxDynamicSharedMemorySize, smem2);

    const int NB_N      = (N_NODES + 255) / 256;
    const int NB_E      = (E + 255) / 256;
    const int NB_GEMM   = (N_NODES + 127) / 128;
    const int NB_GATHER = (N_NODES + 7) / 8;

    // degrees + norms
    zero_deg_kernel<<<NB_N, 256>>>();
    degree_kernel<<<NB_E, 256>>>(src, dst, E);
    rsqrt_kernel<<<NB_N, 256>>>();

    // CSR build (dst-major)
    scan_blocks_kernel<<<SCAN_BLOCKS, 256>>>();
    scan_partials_kernel<<<1, 512>>>();
    scan_add_kernel<<<NB_N, 256>>>();
    csr_fill_kernel<<<NB_E, 256>>>(src, dst, E);

    // layer 1: y = (x * rs_out) @ W1 ; agg[n] = sum_{e: dst=n} y[src]
    gemm_kernel<128, false><<<NB_GEMM, 128, smem1>>>(x, W1, nullptr);
    gather_kernel<false><<<NB_GATHER, 128>>>(nullptr, nullptr);

    // layer 2: h = relu(agg * rs_in + b1); y = (h * rs_out) @ W2
    //          out[n] = (sum y[src]) * rs_in[n] + b2
    gemm_kernel<64, true><<<NB_GEMM, 128, smem2>>>(nullptr, W2, b1);
    gather_kernel<true><<<NB_GATHER, 128>>>((float4*)out, b2);
}